// round 6
// baseline (speedup 1.0000x reference)
#include <cuda_runtime.h>
#include <math.h>

#define BATCH 2
#define NC 8
#define NE 16
#define NSEG 17
#define DD 64
#define HH 128
#define WW 128
#define NVOX (DD*HH*WW)      /* 1048576 per batch */
#define NTOT (BATCH*NVOX)

// ---------------- scratch (device globals; no allocation) ----------------
__device__ int   g_packed[NTOT];       // label | (boundary ? sign bit : 0)
__device__ float g_nll;
__device__ float g_cardp[BATCH][NC];
__device__ float g_inter[BATCH][NC];
__device__ float g_hist[BATCH][NC];    // class counts (= cardg)
__device__ float g_cnt[BATCH][NSEG];
__device__ float g_bcnt[BATCH][NSEG];  // boundary counts per segment
__device__ float g_cnum[BATCH][NSEG][NE];
__device__ float g_centers[BATCH][NSEG][NE];
__device__ float g_pull[BATCH][NSEG];
__device__ float g_push[BATCH];
__device__ float g_normv[BATCH];
__device__ float g_val[BATCH];

// pack two f32 into bf16x2: low = x, high = y
__device__ __forceinline__ unsigned cvt_bf16x2(float x, float y) {
    unsigned d;
    asm("cvt.rn.bf16x2.f32 %0, %1, %2;" : "=r"(d) : "f"(y), "f"(x));
    return d;
}

// one-hot half: (label(p)==n) ? bf16(w(p)) : 0
__device__ __forceinline__ unsigned hb(int p, int n) {
    int l = p & 0x7fffffff;
    unsigned w = (p < 0) ? 0x4120u : 0x3F80u;   // bf16 10.0 : 1.0
    return (l == n) ? w : 0u;
}

// ---------------- zero accumulators ----------------
__global__ void zero_kernel() {
    int t = blockIdx.x * blockDim.x + threadIdx.x;
    if (t < BATCH*NC) {
        (&g_cardp[0][0])[t] = 0.f;
        (&g_inter[0][0])[t] = 0.f;
        (&g_hist[0][0])[t]  = 0.f;
    }
    if (t < BATCH*NSEG) {
        (&g_cnt[0][0])[t]  = 0.f;
        (&g_bcnt[0][0])[t] = 0.f;
        (&g_pull[0][0])[t] = 0.f;
    }
    if (t < BATCH*NSEG*NE) (&g_cnum[0][0][0])[t] = 0.f;
    if (t < BATCH) { g_push[t] = 0.f; g_normv[t] = 0.f; g_val[t] = 0.f; }
    if (t == 0) g_nll = 0.f;
}

// ------ prep: boundary + pack + histograms, 4 voxels/thread ------
__global__ void __launch_bounds__(256) prep_kernel(const int* __restrict__ lab,
                                                   const int* __restrict__ cls) {
    __shared__ float s_cnt[NSEG], s_bcnt[NSEG], s_hist[NC];
    if (threadIdx.x < NSEG) { s_cnt[threadIdx.x] = 0.f; s_bcnt[threadIdx.x] = 0.f; }
    if (threadIdx.x < NC) s_hist[threadIdx.x] = 0.f;
    __syncthreads();

    int tid4 = blockIdx.x * blockDim.x + threadIdx.x;   // one thread = 4 voxels
    int vbase = tid4 * 4;
    int b  = vbase >> 20;
    int v  = vbase & (NVOX - 1);
    int d  = v >> 14;
    int r  = v & 16383;
    int h  = r >> 7;
    int x0 = r & 127;                                   // multiple of 4
    const int* Lb = lab + (size_t)b * NVOX;

    int c0[4];
    bool diff[4] = {false, false, false, false};
    {
        const int* crow = Lb + (d << 14) + (h << 7);
        int4 mid = *(const int4*)(crow + x0);
        c0[0] = mid.x; c0[1] = mid.y; c0[2] = mid.z; c0[3] = mid.w;
    }
#pragma unroll
    for (int dd = -1; dd <= 1; dd++) {
        int zd = min(max(d + dd, 0), DD - 1);
#pragma unroll
        for (int dh = -1; dh <= 1; dh++) {
            int zh = min(max(h + dh, 0), HH - 1);
            const int* row = Lb + (zd << 14) + (zh << 7);
            int left  = __ldg(row + (x0 > 0 ? x0 - 1 : 0));
            int4 mid  = *(const int4*)(row + x0);
            int right = __ldg(row + (x0 < 124 ? x0 + 4 : 127));
            int vals[6] = {left, mid.x, mid.y, mid.z, mid.w, right};
#pragma unroll
            for (int j = 0; j < 4; j++)
                diff[j] |= (vals[j] != c0[j]) | (vals[j+1] != c0[j]) | (vals[j+2] != c0[j]);
        }
    }
    int4 outp;
    outp.x = c0[0] | (diff[0] ? 0x80000000 : 0);
    outp.y = c0[1] | (diff[1] ? 0x80000000 : 0);
    outp.z = c0[2] | (diff[2] ? 0x80000000 : 0);
    outp.w = c0[3] | (diff[3] ? 0x80000000 : 0);
    *(int4*)(g_packed + vbase) = outp;

    int4 cl4 = *(const int4*)(cls + vbase);
#pragma unroll
    for (int j = 0; j < 4; j++) {
        atomicAdd(&s_cnt[c0[j]], 1.f);
        if (diff[j]) atomicAdd(&s_bcnt[c0[j]], 1.f);
    }
    atomicAdd(&s_hist[cl4.x], 1.f);
    atomicAdd(&s_hist[cl4.y], 1.f);
    atomicAdd(&s_hist[cl4.z], 1.f);
    atomicAdd(&s_hist[cl4.w], 1.f);

    __syncthreads();
    if (threadIdx.x < NSEG) {
        if (s_cnt[threadIdx.x]  != 0.f) atomicAdd(&g_cnt[b][threadIdx.x],  s_cnt[threadIdx.x]);
        if (s_bcnt[threadIdx.x] != 0.f) atomicAdd(&g_bcnt[b][threadIdx.x], s_bcnt[threadIdx.x]);
    }
    if (threadIdx.x < NC && s_hist[threadIdx.x] != 0.f)
        atomicAdd(&g_hist[b][threadIdx.x], s_hist[threadIdx.x]);
}

// ---------------- CE + Dice fused pass over sem_logits (vectorized) ---------
__global__ void __launch_bounds__(256) ce_dice_kernel(const float* __restrict__ logits,
                                                      const int* __restrict__ cls) {
    int b = blockIdx.y;
    const float4* lb = (const float4*)(logits + (size_t)b * NC * NVOX);
    const int4*   cb = (const int4*)(cls + (size_t)b * NVOX);

    float r_nll = 0.f;
    float r_cardp[NC], r_inter[NC];
#pragma unroll
    for (int c = 0; c < NC; c++) { r_cardp[c]=0.f; r_inter[c]=0.f; }

    int stride = gridDim.x * blockDim.x;
    for (int i = blockIdx.x * blockDim.x + threadIdx.x; i < NVOX/4; i += stride) {
        float4 x4[NC];
#pragma unroll
        for (int c = 0; c < NC; c++) x4[c] = lb[(size_t)c * (NVOX/4) + i];
        int4 t4 = cb[i];
#pragma unroll
        for (int j = 0; j < 4; j++) {
            float xv[NC];
#pragma unroll
            for (int c = 0; c < NC; c++)
                xv[c] = (j==0) ? x4[c].x : (j==1) ? x4[c].y : (j==2) ? x4[c].z : x4[c].w;
            int t = (j==0) ? t4.x : (j==1) ? t4.y : (j==2) ? t4.z : t4.w;

            float m = xv[0];
#pragma unroll
            for (int c = 1; c < NC; c++) m = fmaxf(m, xv[c]);
            float ex[NC]; float s = 0.f;
#pragma unroll
            for (int c = 0; c < NC; c++) { ex[c] = __expf(xv[c] - m); s += ex[c]; }
            float inv = 1.0f / s;
            float lse = m + __logf(s);
#pragma unroll
            for (int c = 0; c < NC; c++) {
                float p = ex[c] * inv;
                r_cardp[c] += p;
                if (t == c) {
                    r_inter[c] += p;
                    r_nll += lse - xv[c];
                }
            }
        }
    }

    __shared__ float s_acc[17];
    if (threadIdx.x < 17) s_acc[threadIdx.x] = 0.f;
    __syncthreads();
    float vals[17];
    vals[0] = r_nll;
#pragma unroll
    for (int c = 0; c < NC; c++) { vals[1+c]=r_cardp[c]; vals[9+c]=r_inter[c]; }
#pragma unroll
    for (int k = 0; k < 17; k++) {
        float v = vals[k];
#pragma unroll
        for (int o = 16; o; o >>= 1) v += __shfl_xor_sync(0xffffffffu, v, o);
        if ((threadIdx.x & 31) == 0) atomicAdd(&s_acc[k], v);
    }
    __syncthreads();
    int t = threadIdx.x;
    if (t == 0)       atomicAdd(&g_nll, s_acc[0]);
    else if (t < 9)   atomicAdd(&g_cardp[b][t-1], s_acc[t]);
    else if (t < 17)  atomicAdd(&g_inter[b][t-9], s_acc[t]);
}

// ------- pass A: one-hot GEMM via mma.m16n8k16.bf16, permuted k-mapping -----
// voxel(base+4t+0..3) -> k = {2t, 2t+1, 2t+8, 2t+9}: lane loads ONE float4/row.
__global__ void __launch_bounds__(256) segstat_kernel(const float* __restrict__ embed) {
    int b = blockIdx.y;
    const float* eb = embed + (size_t)b * NE * NVOX;
    const int*   pb = g_packed + (size_t)b * NVOX;

    int lane = threadIdx.x & 31;
    int warp = threadIdx.x >> 5;
    int gwarp = blockIdx.x * 8 + warp;
    int nwarps = gridDim.x * 8;

    int t  = lane & 3;       // k-group
    int gq = lane >> 2;      // channel/segment group 0..7

    float d[3][4];
#pragma unroll
    for (int f = 0; f < 3; f++)
#pragma unroll
        for (int r = 0; r < 4; r++) d[f][r] = 0.f;

    const float* r0base = eb + (size_t)gq * NVOX;
    const float* r1base = eb + (size_t)(gq + 8) * NVOX;

    for (int c = gwarp; c < NVOX/16; c += nwarps) {
        int base = c * 16 + 4 * t;
        int4 p4 = *(const int4*)(pb + base);            // broadcast across gq
        float4 a0 = *(const float4*)(r0base + base);    // row gq
        float4 a1 = *(const float4*)(r1base + base);    // row gq+8
        unsigned A0 = cvt_bf16x2(a0.x, a0.y);   // r0, k=2t,2t+1
        unsigned A1 = cvt_bf16x2(a1.x, a1.y);   // r1, k=2t,2t+1
        unsigned A2 = cvt_bf16x2(a0.z, a0.w);   // r0, k=2t+8,2t+9
        unsigned A3 = cvt_bf16x2(a1.z, a1.w);   // r1, k=2t+8,2t+9
#pragma unroll
        for (int f = 0; f < 3; f++) {
            int n = gq + 8*f;
            unsigned B0 = hb(p4.x, n) | (hb(p4.y, n) << 16);   // k=2t,2t+1
            unsigned B1 = hb(p4.z, n) | (hb(p4.w, n) << 16);   // k=2t+8,2t+9
            asm volatile(
                "mma.sync.aligned.m16n8k16.row.col.f32.bf16.bf16.f32 "
                "{%0,%1,%2,%3}, {%4,%5,%6,%7}, {%8,%9}, {%0,%1,%2,%3};"
                : "+f"(d[f][0]), "+f"(d[f][1]), "+f"(d[f][2]), "+f"(d[f][3])
                : "r"(A0), "r"(A1), "r"(A2), "r"(A3), "r"(B0), "r"(B1));
        }
    }

    // D layout: d[f][0]:(ch=gq,  seg=8f+2t)   d[f][1]:(ch=gq,  seg=8f+2t+1)
    //           d[f][2]:(ch=gq+8,seg=8f+2t)   d[f][3]:(ch=gq+8,seg=8f+2t+1)
    __shared__ float s_cnum[NSEG][NE];
    for (int j = threadIdx.x; j < NSEG*NE; j += blockDim.x) (&s_cnum[0][0])[j] = 0.f;
    __syncthreads();
#pragma unroll
    for (int f = 0; f < 3; f++) {
        int n0 = 8*f + 2*t;
        if (n0 < NSEG) {
            atomicAdd(&s_cnum[n0][gq],     d[f][0]);
            atomicAdd(&s_cnum[n0][gq + 8], d[f][2]);
        }
        if (n0 + 1 < NSEG) {
            atomicAdd(&s_cnum[n0+1][gq],     d[f][1]);
            atomicAdd(&s_cnum[n0+1][gq + 8], d[f][3]);
        }
    }
    __syncthreads();
    for (int j = threadIdx.x; j < NSEG*NE; j += blockDim.x) {
        float v = (&s_cnum[0][0])[j];
        if (v != 0.f) atomicAdd(&g_cnum[b][0][0] + j, v);
    }
}

// ---------------- centers + push + norm (tiny) ----------------
__global__ void centers_kernel() {
    int b = blockIdx.x;
    __shared__ float sc[NSEG][NE + 1];
    __shared__ int   s_present[NSEG];
    __shared__ float s_push, s_norm;
    __shared__ int   s_np;
    int tid = threadIdx.x;
    if (tid == 0) { s_push = 0.f; s_norm = 0.f; s_np = 0; }
    for (int j = tid; j < NSEG*NE; j += blockDim.x) {
        int k = j / NE, c = j % NE;
        float wsum = g_cnt[b][k] + 9.0f * g_bcnt[b][k];
        float cen = g_cnum[b][k][c] / (wsum + 1e-8f);
        g_centers[b][k][c] = cen;
        sc[k][c] = cen;
    }
    for (int k = tid; k < NSEG; k += blockDim.x) s_present[k] = (g_cnt[b][k] > 0.f) ? 1 : 0;
    __syncthreads();
    if (tid == 0) {
        int np = 0;
        for (int k = 1; k < NSEG; k++) np += s_present[k];
        s_np = np;
    }
    float pacc = 0.f;
    for (int p = tid; p < 120; p += blockDim.x) {
        int i = 1, rem = p;
        while (rem >= (NSEG - 1) - i) { rem -= (NSEG - 1) - i; i++; }
        int jj = i + 1 + rem;
        float ds = 0.f;
#pragma unroll
        for (int c = 0; c < NE; c++) { float dv = sc[i][c] - sc[jj][c]; ds += dv * dv; }
        float pw = sqrtf(ds);
        float tt = fmaxf(3.0f - pw, 0.f);
        if (s_present[i] && s_present[jj]) pacc += tt * tt;
    }
    atomicAdd(&s_push, pacc);
    float nacc = 0.f;
    for (int k = 1 + tid; k < NSEG; k += blockDim.x) {
        if (s_present[k]) {
            float ds = 0.f;
#pragma unroll
            for (int c = 0; c < NE; c++) ds += sc[k][c] * sc[k][c];
            nacc += sqrtf(ds);
        }
    }
    atomicAdd(&s_norm, nacc);
    __syncthreads();
    if (tid == 0) {
        float np = (float)s_np;
        float npairs = np * (np - 1.f) * 0.5f;
        g_push[b]  = (npairs > 0.f) ? s_push / fmaxf(npairs, 1.f) : 0.f;
        g_normv[b] = (np > 0.f)     ? s_norm / fmaxf(np, 1.f)     : 0.f;
        g_val[b]   = (np > 0.f) ? 1.f : 0.f;
    }
}

// ---------------- pass B: pull (vectorized) ----------------
__global__ void __launch_bounds__(256, 3) pull_kernel(const float* __restrict__ embed) {
    int b = blockIdx.y;
    __shared__ float sc[NSEG][NE + 1];
    __shared__ float s_pull[NSEG];
    for (int j = threadIdx.x; j < NSEG*NE; j += blockDim.x)
        sc[j / NE][j % NE] = g_centers[b][j / NE][j % NE];
    for (int j = threadIdx.x; j < NSEG; j += blockDim.x) s_pull[j] = 0.f;
    __syncthreads();

    const float4* eb = (const float4*)(embed + (size_t)b * NE * NVOX);
    const int4*   pb = (const int4*)(g_packed + (size_t)b * NVOX);

    int stride = gridDim.x * blockDim.x;
    for (int i = blockIdx.x * blockDim.x + threadIdx.x; i < NVOX/4; i += stride) {
        int4 p4 = pb[i];
        int   lv[4]; float wv[4]; float ds[4];
#pragma unroll
        for (int j = 0; j < 4; j++) {
            int p = (j==0) ? p4.x : (j==1) ? p4.y : (j==2) ? p4.z : p4.w;
            lv[j] = p & 0x7fffffff;
            wv[j] = (p < 0) ? 10.f : 1.f;
            ds[j] = 0.f;
        }
#pragma unroll
        for (int half = 0; half < 2; half++) {
            float4 e4[8];
#pragma unroll
            for (int c = 0; c < 8; c++)
                e4[c] = eb[(size_t)(half*8 + c) * (NVOX/4) + i];
#pragma unroll
            for (int c = 0; c < 8; c++) {
                int cc = half*8 + c;
#pragma unroll
                for (int j = 0; j < 4; j++) {
                    float ev = (j==0) ? e4[c].x : (j==1) ? e4[c].y : (j==2) ? e4[c].z : e4[c].w;
                    float dv = ev - sc[lv[j]][cc];
                    ds[j] += dv * dv;
                }
            }
        }
#pragma unroll
        for (int j = 0; j < 4; j++) {
            float dist = sqrtf(ds[j]);
            float tt = fmaxf(dist - 0.5f, 0.f);
            atomicAdd(&s_pull[lv[j]], tt * tt * wv[j]);
        }
    }
    __syncthreads();
    for (int j = threadIdx.x; j < NSEG; j += blockDim.x)
        atomicAdd(&g_pull[b][j], s_pull[j]);
}

// ---------------- final combine ----------------
__global__ void final_kernel(float* __restrict__ out) {
    if (threadIdx.x != 0 || blockIdx.x != 0) return;
    float Nf = (float)NTOT;
    float ce = g_nll / Nf;

    float dsum = 0.f;
    for (int b = 0; b < BATCH; b++)
        for (int c = 0; c < NC; c++)
            dsum += (2.0f * g_inter[b][c] + 1e-5f) /
                    (g_cardp[b][c] + g_hist[b][c] + 1e-5f);
    float dice = 1.0f - dsum / (float)(BATCH * NC);

    float lp = 0.f;
    for (int b = 0; b < BATCH; b++)
        for (int k = 1; k < NSEG; k++)
            if (g_cnt[b][k] > 0.f)
                lp += g_pull[b][k] / fmaxf(g_cnt[b][k], 1.f);

    float push = 0.f, nrm = 0.f, val = 0.f;
    for (int b = 0; b < BATCH; b++) { push += g_push[b]; nrm += g_normv[b]; val += g_val[b]; }

    float ins = (1.0f * lp + 1.0f * push + 0.001f * nrm) / fmaxf(val, 1.f);
    float sem = ce + dice;
    out[0] = sem + ins;
    out[1] = sem;
    out[2] = ce;
    out[3] = dice;
    out[4] = ins;
}

// ---------------- launch ----------------
extern "C" void kernel_launch(void* const* d_in, const int* in_sizes, int n_in,
                              void* d_out, int out_size) {
    const float* sem = (const float*)d_in[0];
    const float* emb = (const float*)d_in[1];
    const int*   cls = (const int*)d_in[2];
    const int*   lab = (const int*)d_in[3];
    float* out = (float*)d_out;

    zero_kernel<<<3, 256>>>();

    prep_kernel<<<NTOT / 1024, 256>>>(lab, cls);

    dim3 g1(296, BATCH);
    ce_dice_kernel<<<g1, 256>>>(sem, cls);

    dim3 g2(592, BATCH);
    segstat_kernel<<<g2, 256>>>(emb);

    centers_kernel<<<BATCH, 128>>>();

    dim3 g3(296, BATCH);
    pull_kernel<<<g3, 256>>>(emb);

    final_kernel<<<1, 32>>>(out);
}

// round 7
// speedup vs baseline: 1.0364x; 1.0364x over previous
#include <cuda_runtime.h>
#include <math.h>

#define BATCH 2
#define NC 8
#define NE 16
#define NSEG 17
#define DD 64
#define HH 128
#define WW 128
#define NVOX (DD*HH*WW)      /* 1048576 per batch */
#define NTOT (BATCH*NVOX)

// ---------------- scratch (device globals; no allocation) ----------------
__device__ int   g_packed[NTOT];       // label | (boundary ? sign bit : 0)
__device__ float g_nll;
__device__ float g_cardp[BATCH][NC];
__device__ float g_inter[BATCH][NC];
__device__ float g_hist[BATCH][NC];    // class counts (= cardg)
__device__ float g_cnt[BATCH][NSEG];
__device__ float g_bcnt[BATCH][NSEG];  // boundary counts per segment
__device__ float g_cnum[BATCH][NSEG][NE];
__device__ float g_centers[BATCH][NSEG][NE];
__device__ float g_pull[BATCH][NSEG];
__device__ float g_push[BATCH];
__device__ float g_normv[BATCH];
__device__ float g_val[BATCH];

// pack two f32 into bf16x2: low = x, high = y
__device__ __forceinline__ unsigned cvt_bf16x2(float x, float y) {
    unsigned d;
    asm("cvt.rn.bf16x2.f32 %0, %1, %2;" : "=r"(d) : "f"(y), "f"(x));
    return d;
}

// one-hot half: (label(p)==n) ? bf16(w(p)) : 0
__device__ __forceinline__ unsigned hb(int p, int n) {
    int l = p & 0x7fffffff;
    unsigned w = (p < 0) ? 0x4120u : 0x3F80u;   // bf16 10.0 : 1.0
    return (l == n) ? w : 0u;
}

// ---------------- zero accumulators ----------------
__global__ void zero_kernel() {
    int t = blockIdx.x * blockDim.x + threadIdx.x;
    if (t < BATCH*NC) {
        (&g_cardp[0][0])[t] = 0.f;
        (&g_inter[0][0])[t] = 0.f;
        (&g_hist[0][0])[t]  = 0.f;
    }
    if (t < BATCH*NSEG) {
        (&g_cnt[0][0])[t]  = 0.f;
        (&g_bcnt[0][0])[t] = 0.f;
        (&g_pull[0][0])[t] = 0.f;
    }
    if (t < BATCH*NSEG*NE) (&g_cnum[0][0][0])[t] = 0.f;
    if (t < BATCH) { g_push[t] = 0.f; g_normv[t] = 0.f; g_val[t] = 0.f; }
    if (t == 0) g_nll = 0.f;
}

// ------ prep: boundary + pack + segment/class histograms (scalar, R5) ------
__global__ void __launch_bounds__(256) prep_kernel(const int* __restrict__ lab,
                                                   const int* __restrict__ cls) {
    __shared__ float s_cnt[NSEG], s_bcnt[NSEG], s_hist[NC];
    if (threadIdx.x < NSEG) { s_cnt[threadIdx.x] = 0.f; s_bcnt[threadIdx.x] = 0.f; }
    if (threadIdx.x < NC) s_hist[threadIdx.x] = 0.f;
    __syncthreads();

    int idx = blockIdx.x * blockDim.x + threadIdx.x;
    int b = idx >> 20;
    int v = idx & (NVOX - 1);
    int d = v >> 14;
    int r = v & 16383;
    int h = r >> 7;
    int x = r & 127;
    const int* Lb = lab + (size_t)b * NVOX;
    int c0 = Lb[v];
    bool diff = false;
#pragma unroll
    for (int dd = -1; dd <= 1; dd++) {
        int zd = min(max(d + dd, 0), DD - 1);
#pragma unroll
        for (int dh = -1; dh <= 1; dh++) {
            int zh = min(max(h + dh, 0), HH - 1);
#pragma unroll
            for (int dx = -1; dx <= 1; dx++) {
                int zx = min(max(x + dx, 0), WW - 1);
                diff |= (Lb[(zd << 14) + (zh << 7) + zx] != c0);
            }
        }
    }
    g_packed[idx] = c0 | (diff ? 0x80000000 : 0);

    atomicAdd(&s_cnt[c0], 1.f);
    if (diff) atomicAdd(&s_bcnt[c0], 1.f);
    int cl = cls[idx];
    atomicAdd(&s_hist[cl], 1.f);

    __syncthreads();
    if (threadIdx.x < NSEG) {
        if (s_cnt[threadIdx.x]  != 0.f) atomicAdd(&g_cnt[b][threadIdx.x],  s_cnt[threadIdx.x]);
        if (s_bcnt[threadIdx.x] != 0.f) atomicAdd(&g_bcnt[b][threadIdx.x], s_bcnt[threadIdx.x]);
    }
    if (threadIdx.x < NC && s_hist[threadIdx.x] != 0.f)
        atomicAdd(&g_hist[b][threadIdx.x], s_hist[threadIdx.x]);
}

// ---------------- CE + Dice fused pass over sem_logits (vectorized) ---------
__global__ void __launch_bounds__(256, 2) ce_dice_kernel(const float* __restrict__ logits,
                                                         const int* __restrict__ cls) {
    int b = blockIdx.y;
    const float4* lb = (const float4*)(logits + (size_t)b * NC * NVOX);
    const int4*   cb = (const int4*)(cls + (size_t)b * NVOX);

    float r_nll = 0.f;
    float r_cardp[NC], r_inter[NC];
#pragma unroll
    for (int c = 0; c < NC; c++) { r_cardp[c]=0.f; r_inter[c]=0.f; }

    int stride = gridDim.x * blockDim.x;
    for (int i = blockIdx.x * blockDim.x + threadIdx.x; i < NVOX/4; i += stride) {
        int4 t4 = cb[i];
        float4 x4[NC];
#pragma unroll
        for (int c = 0; c < NC; c++) x4[c] = lb[(size_t)c * (NVOX/4) + i];
#pragma unroll
        for (int j = 0; j < 4; j++) {
            float xv[NC];
#pragma unroll
            for (int c = 0; c < NC; c++)
                xv[c] = (j==0) ? x4[c].x : (j==1) ? x4[c].y : (j==2) ? x4[c].z : x4[c].w;
            int t = (j==0) ? t4.x : (j==1) ? t4.y : (j==2) ? t4.z : t4.w;

            float m = xv[0];
#pragma unroll
            for (int c = 1; c < NC; c++) m = fmaxf(m, xv[c]);
            float ex[NC]; float s = 0.f;
#pragma unroll
            for (int c = 0; c < NC; c++) { ex[c] = __expf(xv[c] - m); s += ex[c]; }
            float inv = 1.0f / s;
            float lse = m + __logf(s);
#pragma unroll
            for (int c = 0; c < NC; c++) {
                float p = ex[c] * inv;
                r_cardp[c] += p;
                if (t == c) {
                    r_inter[c] += p;
                    r_nll += lse - xv[c];
                }
            }
        }
    }

    __shared__ float s_acc[17];
    if (threadIdx.x < 17) s_acc[threadIdx.x] = 0.f;
    __syncthreads();
    float vals[17];
    vals[0] = r_nll;
#pragma unroll
    for (int c = 0; c < NC; c++) { vals[1+c]=r_cardp[c]; vals[9+c]=r_inter[c]; }
#pragma unroll
    for (int k = 0; k < 17; k++) {
        float v = vals[k];
#pragma unroll
        for (int o = 16; o; o >>= 1) v += __shfl_xor_sync(0xffffffffu, v, o);
        if ((threadIdx.x & 31) == 0) atomicAdd(&s_acc[k], v);
    }
    __syncthreads();
    int t = threadIdx.x;
    if (t == 0)       atomicAdd(&g_nll, s_acc[0]);
    else if (t < 9)   atomicAdd(&g_cardp[b][t-1], s_acc[t]);
    else if (t < 17)  atomicAdd(&g_inter[b][t-9], s_acc[t]);
}

// ------- pass A: one-hot GEMM via mma.m16n8k16.bf16, 2 chunks/iteration -----
// voxel(base+4t+0..3) -> k = {2t, 2t+1, 2t+8, 2t+9}: lane loads ONE float4/row.
__global__ void __launch_bounds__(256) segstat_kernel(const float* __restrict__ embed) {
    int b = blockIdx.y;
    const float* eb = embed + (size_t)b * NE * NVOX;
    const int*   pb = g_packed + (size_t)b * NVOX;

    int lane = threadIdx.x & 31;
    int warp = threadIdx.x >> 5;
    int gwarp = blockIdx.x * 8 + warp;
    int nwarps = gridDim.x * 8;

    int t  = lane & 3;       // k-group
    int gq = lane >> 2;      // channel/segment group 0..7

    float d[3][4];
#pragma unroll
    for (int f = 0; f < 3; f++)
#pragma unroll
        for (int r = 0; r < 4; r++) d[f][r] = 0.f;

    const float* r0base = eb + (size_t)gq * NVOX;
    const float* r1base = eb + (size_t)(gq + 8) * NVOX;

    // pair of 16-voxel chunks per iteration: 6 front-batched LDG.128
    for (int pp = gwarp; pp < NVOX/32; pp += nwarps) {
        int base0 = pp * 32 + 4 * t;
        int base1 = base0 + 16;
        int4   pA  = *(const int4*)(pb + base0);
        int4   pB  = *(const int4*)(pb + base1);
        float4 a0A = *(const float4*)(r0base + base0);
        float4 a1A = *(const float4*)(r1base + base0);
        float4 a0B = *(const float4*)(r0base + base1);
        float4 a1B = *(const float4*)(r1base + base1);

        unsigned A0 = cvt_bf16x2(a0A.x, a0A.y);
        unsigned A1 = cvt_bf16x2(a1A.x, a1A.y);
        unsigned A2 = cvt_bf16x2(a0A.z, a0A.w);
        unsigned A3 = cvt_bf16x2(a1A.z, a1A.w);
#pragma unroll
        for (int f = 0; f < 3; f++) {
            int n = gq + 8*f;
            unsigned B0 = hb(pA.x, n) | (hb(pA.y, n) << 16);
            unsigned B1 = hb(pA.z, n) | (hb(pA.w, n) << 16);
            asm volatile(
                "mma.sync.aligned.m16n8k16.row.col.f32.bf16.bf16.f32 "
                "{%0,%1,%2,%3}, {%4,%5,%6,%7}, {%8,%9}, {%0,%1,%2,%3};"
                : "+f"(d[f][0]), "+f"(d[f][1]), "+f"(d[f][2]), "+f"(d[f][3])
                : "r"(A0), "r"(A1), "r"(A2), "r"(A3), "r"(B0), "r"(B1));
        }
        unsigned C0 = cvt_bf16x2(a0B.x, a0B.y);
        unsigned C1 = cvt_bf16x2(a1B.x, a1B.y);
        unsigned C2 = cvt_bf16x2(a0B.z, a0B.w);
        unsigned C3 = cvt_bf16x2(a1B.z, a1B.w);
#pragma unroll
        for (int f = 0; f < 3; f++) {
            int n = gq + 8*f;
            unsigned B0 = hb(pB.x, n) | (hb(pB.y, n) << 16);
            unsigned B1 = hb(pB.z, n) | (hb(pB.w, n) << 16);
            asm volatile(
                "mma.sync.aligned.m16n8k16.row.col.f32.bf16.bf16.f32 "
                "{%0,%1,%2,%3}, {%4,%5,%6,%7}, {%8,%9}, {%0,%1,%2,%3};"
                : "+f"(d[f][0]), "+f"(d[f][1]), "+f"(d[f][2]), "+f"(d[f][3])
                : "r"(C0), "r"(C1), "r"(C2), "r"(C3), "r"(B0), "r"(B1));
        }
    }

    // D layout: d[f][0]:(ch=gq,  seg=8f+2t)   d[f][1]:(ch=gq,  seg=8f+2t+1)
    //           d[f][2]:(ch=gq+8,seg=8f+2t)   d[f][3]:(ch=gq+8,seg=8f+2t+1)
    __shared__ float s_cnum[NSEG][NE];
    for (int j = threadIdx.x; j < NSEG*NE; j += blockDim.x) (&s_cnum[0][0])[j] = 0.f;
    __syncthreads();
#pragma unroll
    for (int f = 0; f < 3; f++) {
        int n0 = 8*f + 2*t;
        if (n0 < NSEG) {
            atomicAdd(&s_cnum[n0][gq],     d[f][0]);
            atomicAdd(&s_cnum[n0][gq + 8], d[f][2]);
        }
        if (n0 + 1 < NSEG) {
            atomicAdd(&s_cnum[n0+1][gq],     d[f][1]);
            atomicAdd(&s_cnum[n0+1][gq + 8], d[f][3]);
        }
    }
    __syncthreads();
    for (int j = threadIdx.x; j < NSEG*NE; j += blockDim.x) {
        float v = (&s_cnum[0][0])[j];
        if (v != 0.f) atomicAdd(&g_cnum[b][0][0] + j, v);
    }
}

// ---------------- centers + push + norm (tiny) ----------------
__global__ void centers_kernel() {
    int b = blockIdx.x;
    __shared__ float sc[NSEG][NE + 1];
    __shared__ int   s_present[NSEG];
    __shared__ float s_push, s_norm;
    __shared__ int   s_np;
    int tid = threadIdx.x;
    if (tid == 0) { s_push = 0.f; s_norm = 0.f; s_np = 0; }
    for (int j = tid; j < NSEG*NE; j += blockDim.x) {
        int k = j / NE, c = j % NE;
        float wsum = g_cnt[b][k] + 9.0f * g_bcnt[b][k];
        float cen = g_cnum[b][k][c] / (wsum + 1e-8f);
        g_centers[b][k][c] = cen;
        sc[k][c] = cen;
    }
    for (int k = tid; k < NSEG; k += blockDim.x) s_present[k] = (g_cnt[b][k] > 0.f) ? 1 : 0;
    __syncthreads();
    if (tid == 0) {
        int np = 0;
        for (int k = 1; k < NSEG; k++) np += s_present[k];
        s_np = np;
    }
    float pacc = 0.f;
    for (int p = tid; p < 120; p += blockDim.x) {
        int i = 1, rem = p;
        while (rem >= (NSEG - 1) - i) { rem -= (NSEG - 1) - i; i++; }
        int jj = i + 1 + rem;
        float ds = 0.f;
#pragma unroll
        for (int c = 0; c < NE; c++) { float dv = sc[i][c] - sc[jj][c]; ds += dv * dv; }
        float pw = sqrtf(ds);
        float tt = fmaxf(3.0f - pw, 0.f);
        if (s_present[i] && s_present[jj]) pacc += tt * tt;
    }
    atomicAdd(&s_push, pacc);
    float nacc = 0.f;
    for (int k = 1 + tid; k < NSEG; k += blockDim.x) {
        if (s_present[k]) {
            float ds = 0.f;
#pragma unroll
            for (int c = 0; c < NE; c++) ds += sc[k][c] * sc[k][c];
            nacc += sqrtf(ds);
        }
    }
    atomicAdd(&s_norm, nacc);
    __syncthreads();
    if (tid == 0) {
        float np = (float)s_np;
        float npairs = np * (np - 1.f) * 0.5f;
        g_push[b]  = (npairs > 0.f) ? s_push / fmaxf(npairs, 1.f) : 0.f;
        g_normv[b] = (np > 0.f)     ? s_norm / fmaxf(np, 1.f)     : 0.f;
        g_val[b]   = (np > 0.f) ? 1.f : 0.f;
    }
}

// ---------------- pass B: pull (all loads batched) ----------------
__global__ void __launch_bounds__(256, 2) pull_kernel(const float* __restrict__ embed) {
    int b = blockIdx.y;
    __shared__ float sc[NSEG][NE + 1];
    __shared__ float s_pull[NSEG];
    for (int j = threadIdx.x; j < NSEG*NE; j += blockDim.x)
        sc[j / NE][j % NE] = g_centers[b][j / NE][j % NE];
    for (int j = threadIdx.x; j < NSEG; j += blockDim.x) s_pull[j] = 0.f;
    __syncthreads();

    const float4* eb = (const float4*)(embed + (size_t)b * NE * NVOX);
    const int4*   pb = (const int4*)(g_packed + (size_t)b * NVOX);

    int stride = gridDim.x * blockDim.x;
    for (int i = blockIdx.x * blockDim.x + threadIdx.x; i < NVOX/4; i += stride) {
        int4 p4 = pb[i];
        float4 e4[NE];
#pragma unroll
        for (int c = 0; c < NE; c++)
            e4[c] = eb[(size_t)c * (NVOX/4) + i];

        int   lv[4]; float wv[4]; float ds[4];
#pragma unroll
        for (int j = 0; j < 4; j++) {
            int p = (j==0) ? p4.x : (j==1) ? p4.y : (j==2) ? p4.z : p4.w;
            lv[j] = p & 0x7fffffff;
            wv[j] = (p < 0) ? 10.f : 1.f;
            ds[j] = 0.f;
        }
#pragma unroll
        for (int c = 0; c < NE; c++) {
#pragma unroll
            for (int j = 0; j < 4; j++) {
                float ev = (j==0) ? e4[c].x : (j==1) ? e4[c].y : (j==2) ? e4[c].z : e4[c].w;
                float dv = ev - sc[lv[j]][c];
                ds[j] += dv * dv;
            }
        }
#pragma unroll
        for (int j = 0; j < 4; j++) {
            float dist = sqrtf(ds[j]);
            float tt = fmaxf(dist - 0.5f, 0.f);
            atomicAdd(&s_pull[lv[j]], tt * tt * wv[j]);
        }
    }
    __syncthreads();
    for (int j = threadIdx.x; j < NSEG; j += blockDim.x)
        atomicAdd(&g_pull[b][j], s_pull[j]);
}

// ---------------- final combine ----------------
__global__ void final_kernel(float* __restrict__ out) {
    if (threadIdx.x != 0 || blockIdx.x != 0) return;
    float Nf = (float)NTOT;
    float ce = g_nll / Nf;

    float dsum = 0.f;
    for (int b = 0; b < BATCH; b++)
        for (int c = 0; c < NC; c++)
            dsum += (2.0f * g_inter[b][c] + 1e-5f) /
                    (g_cardp[b][c] + g_hist[b][c] + 1e-5f);
    float dice = 1.0f - dsum / (float)(BATCH * NC);

    float lp = 0.f;
    for (int b = 0; b < BATCH; b++)
        for (int k = 1; k < NSEG; k++)
            if (g_cnt[b][k] > 0.f)
                lp += g_pull[b][k] / fmaxf(g_cnt[b][k], 1.f);

    float push = 0.f, nrm = 0.f, val = 0.f;
    for (int b = 0; b < BATCH; b++) { push += g_push[b]; nrm += g_normv[b]; val += g_val[b]; }

    float ins = (1.0f * lp + 1.0f * push + 0.001f * nrm) / fmaxf(val, 1.f);
    float sem = ce + dice;
    out[0] = sem + ins;
    out[1] = sem;
    out[2] = ce;
    out[3] = dice;
    out[4] = ins;
}

// ---------------- launch ----------------
extern "C" void kernel_launch(void* const* d_in, const int* in_sizes, int n_in,
                              void* d_out, int out_size) {
    const float* sem = (const float*)d_in[0];
    const float* emb = (const float*)d_in[1];
    const int*   cls = (const int*)d_in[2];
    const int*   lab = (const int*)d_in[3];
    float* out = (float*)d_out;

    zero_kernel<<<3, 256>>>();

    prep_kernel<<<NTOT / 256, 256>>>(lab, cls);

    dim3 g1(296, BATCH);
    ce_dice_kernel<<<g1, 256>>>(sem, cls);

    dim3 g2(592, BATCH);
    segstat_kernel<<<g2, 256>>>(emb);

    centers_kernel<<<BATCH, 128>>>();

    dim3 g3(296, BATCH);
    pull_kernel<<<g3, 256>>>(emb);

    final_kernel<<<1, 32>>>(out);
}

// round 9
// speedup vs baseline: 1.2256x; 1.1826x over previous
#include <cuda_runtime.h>
#include <math.h>

#define BATCH 2
#define NC 8
#define NE 16
#define NSEG 17
#define DD 64
#define HH 128
#define WW 128
#define NVOX (DD*HH*WW)      /* 1048576 per batch */
#define NTOT (BATCH*NVOX)

#define SEG_X 296            /* segstat blocks per batch in fused kernel */
#define CE_X  296            /* ce_dice blocks per batch in fused kernel */

// ---------------- scratch (device globals; zero-initialized at load) --------
__device__ int   g_packed[NTOT];       // label | (boundary ? sign bit : 0)
__device__ float g_nll;
__device__ float g_cardp[BATCH][NC];
__device__ float g_inter[BATCH][NC];
__device__ float g_hist[BATCH][NC];    // class counts (= cardg)
__device__ float g_cnt[BATCH][NSEG];
__device__ float g_bcnt[BATCH][NSEG];  // boundary counts per segment
__device__ float g_cnum[BATCH][NSEG][NE];
__device__ float g_pull[BATCH][NSEG];

// pack two f32 into bf16x2: low = x, high = y
__device__ __forceinline__ unsigned cvt_bf16x2(float x, float y) {
    unsigned d;
    asm("cvt.rn.bf16x2.f32 %0, %1, %2;" : "=r"(d) : "f"(y), "f"(x));
    return d;
}

// one-hot half: (label(p)==n) ? bf16(w(p)) : 0
__device__ __forceinline__ unsigned hb(int p, int n) {
    int l = p & 0x7fffffff;
    unsigned w = (p < 0) ? 0x4120u : 0x3F80u;   // bf16 10.0 : 1.0
    return (l == n) ? w : 0u;
}

// ------ prep: boundary + pack + segment/class histograms ------
__global__ void __launch_bounds__(256) prep_kernel(const int* __restrict__ lab,
                                                   const int* __restrict__ cls) {
    __shared__ float s_cnt[NSEG], s_bcnt[NSEG], s_hist[NC];
    if (threadIdx.x < NSEG) { s_cnt[threadIdx.x] = 0.f; s_bcnt[threadIdx.x] = 0.f; }
    if (threadIdx.x < NC) s_hist[threadIdx.x] = 0.f;
    __syncthreads();

    int idx = blockIdx.x * blockDim.x + threadIdx.x;
    int b = idx >> 20;
    int v = idx & (NVOX - 1);
    int d = v >> 14;
    int r = v & 16383;
    int h = r >> 7;
    int x = r & 127;
    const int* Lb = lab + (size_t)b * NVOX;
    int c0 = Lb[v];
    bool diff = false;
#pragma unroll
    for (int dd = -1; dd <= 1; dd++) {
        int zd = min(max(d + dd, 0), DD - 1);
#pragma unroll
        for (int dh = -1; dh <= 1; dh++) {
            int zh = min(max(h + dh, 0), HH - 1);
#pragma unroll
            for (int dx = -1; dx <= 1; dx++) {
                int zx = min(max(x + dx, 0), WW - 1);
                diff |= (Lb[(zd << 14) + (zh << 7) + zx] != c0);
            }
        }
    }
    g_packed[idx] = c0 | (diff ? 0x80000000 : 0);

    atomicAdd(&s_cnt[c0], 1.f);
    if (diff) atomicAdd(&s_bcnt[c0], 1.f);
    int cl = cls[idx];
    atomicAdd(&s_hist[cl], 1.f);

    __syncthreads();
    if (threadIdx.x < NSEG) {
        if (s_cnt[threadIdx.x]  != 0.f) atomicAdd(&g_cnt[b][threadIdx.x],  s_cnt[threadIdx.x]);
        if (s_bcnt[threadIdx.x] != 0.f) atomicAdd(&g_bcnt[b][threadIdx.x], s_bcnt[threadIdx.x]);
    }
    if (threadIdx.x < NC && s_hist[threadIdx.x] != 0.f)
        atomicAdd(&g_hist[b][threadIdx.x], s_hist[threadIdx.x]);
}

// ------- segstat body: one-hot GEMM via mma.m16n8k16.bf16 -------
__device__ __forceinline__ void segstat_body(const float* __restrict__ embed,
                                             int b, int bx) {
    const float* eb = embed + (size_t)b * NE * NVOX;
    const int*   pb = g_packed + (size_t)b * NVOX;

    int lane = threadIdx.x & 31;
    int warp = threadIdx.x >> 5;
    int gwarp = bx * 8 + warp;
    int nwarps = SEG_X * 8;

    int t  = lane & 3;       // k-group
    int gq = lane >> 2;      // channel/segment group 0..7

    float d[3][4];
#pragma unroll
    for (int f = 0; f < 3; f++)
#pragma unroll
        for (int r = 0; r < 4; r++) d[f][r] = 0.f;

    const float* r0base = eb + (size_t)gq * NVOX;
    const float* r1base = eb + (size_t)(gq + 8) * NVOX;

    for (int pp = gwarp; pp < NVOX/32; pp += nwarps) {
        int base0 = pp * 32 + 4 * t;
        int base1 = base0 + 16;
        int4   pA  = *(const int4*)(pb + base0);
        int4   pB  = *(const int4*)(pb + base1);
        float4 a0A = *(const float4*)(r0base + base0);
        float4 a1A = *(const float4*)(r1base + base0);
        float4 a0B = *(const float4*)(r0base + base1);
        float4 a1B = *(const float4*)(r1base + base1);

        unsigned A0 = cvt_bf16x2(a0A.x, a0A.y);
        unsigned A1 = cvt_bf16x2(a1A.x, a1A.y);
        unsigned A2 = cvt_bf16x2(a0A.z, a0A.w);
        unsigned A3 = cvt_bf16x2(a1A.z, a1A.w);
#pragma unroll
        for (int f = 0; f < 3; f++) {
            int n = gq + 8*f;
            unsigned B0 = hb(pA.x, n) | (hb(pA.y, n) << 16);
            unsigned B1 = hb(pA.z, n) | (hb(pA.w, n) << 16);
            asm volatile(
                "mma.sync.aligned.m16n8k16.row.col.f32.bf16.bf16.f32 "
                "{%0,%1,%2,%3}, {%4,%5,%6,%7}, {%8,%9}, {%0,%1,%2,%3};"
                : "+f"(d[f][0]), "+f"(d[f][1]), "+f"(d[f][2]), "+f"(d[f][3])
                : "r"(A0), "r"(A1), "r"(A2), "r"(A3), "r"(B0), "r"(B1));
        }
        unsigned C0 = cvt_bf16x2(a0B.x, a0B.y);
        unsigned C1 = cvt_bf16x2(a1B.x, a1B.y);
        unsigned C2 = cvt_bf16x2(a0B.z, a0B.w);
        unsigned C3 = cvt_bf16x2(a1B.z, a1B.w);
#pragma unroll
        for (int f = 0; f < 3; f++) {
            int n = gq + 8*f;
            unsigned B0 = hb(pB.x, n) | (hb(pB.y, n) << 16);
            unsigned B1 = hb(pB.z, n) | (hb(pB.w, n) << 16);
            asm volatile(
                "mma.sync.aligned.m16n8k16.row.col.f32.bf16.bf16.f32 "
                "{%0,%1,%2,%3}, {%4,%5,%6,%7}, {%8,%9}, {%0,%1,%2,%3};"
                : "+f"(d[f][0]), "+f"(d[f][1]), "+f"(d[f][2]), "+f"(d[f][3])
                : "r"(C0), "r"(C1), "r"(C2), "r"(C3), "r"(B0), "r"(B1));
        }
    }

    __shared__ float s_cnum[NSEG][NE];
    for (int j = threadIdx.x; j < NSEG*NE; j += blockDim.x) (&s_cnum[0][0])[j] = 0.f;
    __syncthreads();
#pragma unroll
    for (int f = 0; f < 3; f++) {
        int n0 = 8*f + 2*t;
        if (n0 < NSEG) {
            atomicAdd(&s_cnum[n0][gq],     d[f][0]);
            atomicAdd(&s_cnum[n0][gq + 8], d[f][2]);
        }
        if (n0 + 1 < NSEG) {
            atomicAdd(&s_cnum[n0+1][gq],     d[f][1]);
            atomicAdd(&s_cnum[n0+1][gq + 8], d[f][3]);
        }
    }
    __syncthreads();
    for (int j = threadIdx.x; j < NSEG*NE; j += blockDim.x) {
        float v = (&s_cnum[0][0])[j];
        if (v != 0.f) atomicAdd(&g_cnum[b][0][0] + j, v);
    }
}

// ------- ce_dice body: float2 (2 voxels/thread/iter) to fit registers -------
__device__ __forceinline__ void ce_body(const float* __restrict__ logits,
                                        const int* __restrict__ cls,
                                        int b, int bx) {
    const float2* lb = (const float2*)(logits + (size_t)b * NC * NVOX);
    const int2*   cb = (const int2*)(cls + (size_t)b * NVOX);

    float r_nll = 0.f;
    float r_cardp[NC], r_inter[NC];
#pragma unroll
    for (int c = 0; c < NC; c++) { r_cardp[c]=0.f; r_inter[c]=0.f; }

    int stride = CE_X * 256;
    for (int i = bx * 256 + threadIdx.x; i < NVOX/2; i += stride) {
        int2 t2 = cb[i];
        float2 x2[NC];
#pragma unroll
        for (int c = 0; c < NC; c++) x2[c] = lb[(size_t)c * (NVOX/2) + i];
#pragma unroll
        for (int j = 0; j < 2; j++) {
            float xv[NC];
#pragma unroll
            for (int c = 0; c < NC; c++)
                xv[c] = j ? x2[c].y : x2[c].x;
            int t = j ? t2.y : t2.x;

            float m = xv[0];
#pragma unroll
            for (int c = 1; c < NC; c++) m = fmaxf(m, xv[c]);
            float ex[NC]; float s = 0.f;
#pragma unroll
            for (int c = 0; c < NC; c++) { ex[c] = __expf(xv[c] - m); s += ex[c]; }
            float inv = 1.0f / s;
            float lse = m + __logf(s);
#pragma unroll
            for (int c = 0; c < NC; c++) {
                float p = ex[c] * inv;
                r_cardp[c] += p;
                if (t == c) {
                    r_inter[c] += p;
                    r_nll += lse - xv[c];
                }
            }
        }
    }

    __shared__ float s_acc[17];
    if (threadIdx.x < 17) s_acc[threadIdx.x] = 0.f;
    __syncthreads();
    float vals[17];
    vals[0] = r_nll;
#pragma unroll
    for (int c = 0; c < NC; c++) { vals[1+c]=r_cardp[c]; vals[9+c]=r_inter[c]; }
#pragma unroll
    for (int k = 0; k < 17; k++) {
        float v = vals[k];
#pragma unroll
        for (int o = 16; o; o >>= 1) v += __shfl_xor_sync(0xffffffffu, v, o);
        if ((threadIdx.x & 31) == 0) atomicAdd(&s_acc[k], v);
    }
    __syncthreads();
    int t = threadIdx.x;
    if (t == 0)       atomicAdd(&g_nll, s_acc[0]);
    else if (t < 9)   atomicAdd(&g_cardp[b][t-1], s_acc[t]);
    else if (t < 17)  atomicAdd(&g_inter[b][t-9], s_acc[t]);
}

// ------- fused main pass: segstat blocks + ce_dice blocks in one launch -----
__global__ void __launch_bounds__(256, 4) fused_main(const float* __restrict__ embed,
                                                     const float* __restrict__ logits,
                                                     const int* __restrict__ cls) {
    int b = blockIdx.y;
    if (blockIdx.x < SEG_X) segstat_body(embed, b, blockIdx.x);
    else                    ce_body(logits, cls, b, blockIdx.x - SEG_X);
}

// ---------------- pass B: pull (centers computed per block) ----------------
__global__ void __launch_bounds__(256, 2) pull_kernel(const float* __restrict__ embed) {
    int b = blockIdx.y;
    __shared__ float sc[NSEG][NE + 1];
    __shared__ float s_pull[NSEG];
    for (int j = threadIdx.x; j < NSEG*NE; j += blockDim.x) {
        int k = j / NE, c = j % NE;
        float wsum = g_cnt[b][k] + 9.0f * g_bcnt[b][k];
        sc[k][c] = g_cnum[b][k][c] / (wsum + 1e-8f);
    }
    for (int j = threadIdx.x; j < NSEG; j += blockDim.x) s_pull[j] = 0.f;
    __syncthreads();

    const float4* eb = (const float4*)(embed + (size_t)b * NE * NVOX);
    const int4*   pb = (const int4*)(g_packed + (size_t)b * NVOX);

    int stride = gridDim.x * blockDim.x;
    for (int i = blockIdx.x * blockDim.x + threadIdx.x; i < NVOX/4; i += stride) {
        int4 p4 = pb[i];
        float4 e4[NE];
#pragma unroll
        for (int c = 0; c < NE; c++)
            e4[c] = eb[(size_t)c * (NVOX/4) + i];

        int   lv[4]; float wv[4]; float ds[4];
#pragma unroll
        for (int j = 0; j < 4; j++) {
            int p = (j==0) ? p4.x : (j==1) ? p4.y : (j==2) ? p4.z : p4.w;
            lv[j] = p & 0x7fffffff;
            wv[j] = (p < 0) ? 10.f : 1.f;
            ds[j] = 0.f;
        }
#pragma unroll
        for (int c = 0; c < NE; c++) {
#pragma unroll
            for (int j = 0; j < 4; j++) {
                float ev = (j==0) ? e4[c].x : (j==1) ? e4[c].y : (j==2) ? e4[c].z : e4[c].w;
                float dv = ev - sc[lv[j]][c];
                ds[j] += dv * dv;
            }
        }
#pragma unroll
        for (int j = 0; j < 4; j++) {
            float dist = sqrtf(ds[j]);
            float tt = fmaxf(dist - 0.5f, 0.f);
            atomicAdd(&s_pull[lv[j]], tt * tt * wv[j]);
        }
    }
    __syncthreads();
    for (int j = threadIdx.x; j < NSEG; j += blockDim.x)
        atomicAdd(&g_pull[b][j], s_pull[j]);
}

// -------- final: centers/push/norm + combine + self-clean accumulators ------
__global__ void final_kernel(float* __restrict__ out) {
    int lane = threadIdx.x;   // launched with 32 threads
    __shared__ float sc[NSEG][NE];

    float lp_sum = 0.f, push_sum = 0.f, norm_sum = 0.f, val_sum = 0.f;
    for (int b = 0; b < BATCH; b++) {
        for (int j = lane; j < NSEG*NE; j += 32) {
            int k = j / NE, c = j % NE;
            float wsum = g_cnt[b][k] + 9.0f * g_bcnt[b][k];
            sc[k][c] = g_cnum[b][k][c] / (wsum + 1e-8f);
        }
        __syncwarp();

        int pres_lane = (lane >= 1 && lane < NSEG) ? (g_cnt[b][lane] > 0.f ? 1 : 0) : 0;
        unsigned mask = __ballot_sync(0xffffffffu, pres_lane);
        float np = (float)__popc(mask);

        // pull normalization
        float lp = pres_lane ? g_pull[b][lane] / fmaxf(g_cnt[b][lane], 1.f) : 0.f;
#pragma unroll
        for (int o = 16; o; o >>= 1) lp += __shfl_xor_sync(0xffffffffu, lp, o);

        // push over 120 pairs
        float pacc = 0.f;
        for (int pp = lane; pp < 120; pp += 32) {
            int i = 1, rem = pp;
            while (rem >= (NSEG - 1) - i) { rem -= (NSEG - 1) - i; i++; }
            int jj = i + 1 + rem;
            float ds = 0.f;
#pragma unroll
            for (int c = 0; c < NE; c++) { float dv = sc[i][c] - sc[jj][c]; ds += dv * dv; }
            float pw = sqrtf(ds);
            float tt = fmaxf(3.0f - pw, 0.f);
            if (((mask >> i) & 1) && ((mask >> jj) & 1)) pacc += tt * tt;
        }
#pragma unroll
        for (int o = 16; o; o >>= 1) pacc += __shfl_xor_sync(0xffffffffu, pacc, o);

        // norm
        float nacc = 0.f;
        if (pres_lane) {
            float ds = 0.f;
#pragma unroll
            for (int c = 0; c < NE; c++) ds += sc[lane][c] * sc[lane][c];
            nacc = sqrtf(ds);
        }
#pragma unroll
        for (int o = 16; o; o >>= 1) nacc += __shfl_xor_sync(0xffffffffu, nacc, o);

        float npairs = np * (np - 1.f) * 0.5f;
        lp_sum   += lp;
        push_sum += (npairs > 0.f) ? pacc / fmaxf(npairs, 1.f) : 0.f;
        norm_sum += (np > 0.f)     ? nacc / fmaxf(np, 1.f)     : 0.f;
        val_sum  += (np > 0.f) ? 1.f : 0.f;
        __syncwarp();
    }

    float Nf = (float)NTOT;
    float ce = g_nll / Nf;
    float dsum = 0.f;
    for (int b = 0; b < BATCH; b++)
        for (int c = 0; c < NC; c++)
            dsum += (2.0f * g_inter[b][c] + 1e-5f) /
                    (g_cardp[b][c] + g_hist[b][c] + 1e-5f);
    float dice = 1.0f - dsum / (float)(BATCH * NC);

    float ins = (lp_sum + push_sum + 0.001f * norm_sum) / fmaxf(val_sum, 1.f);
    float sem = ce + dice;
    if (lane == 0) {
        out[0] = sem + ins;
        out[1] = sem;
        out[2] = ce;
        out[3] = dice;
        out[4] = ins;
    }

    // self-clean accumulators so the next graph replay starts from zero
    for (int j = lane; j < BATCH*NC; j += 32) {
        (&g_cardp[0][0])[j] = 0.f;
        (&g_inter[0][0])[j] = 0.f;
        (&g_hist[0][0])[j]  = 0.f;
    }
    for (int j = lane; j < BATCH*NSEG; j += 32) {
        (&g_cnt[0][0])[j]  = 0.f;
        (&g_bcnt[0][0])[j] = 0.f;
        (&g_pull[0][0])[j] = 0.f;
    }
    for (int j = lane; j < BATCH*NSEG*NE; j += 32)
        (&g_cnum[0][0][0])[j] = 0.f;
    if (lane == 0) g_nll = 0.f;
}

// ---------------- launch ----------------
extern "C" void kernel_launch(void* const* d_in, const int* in_sizes, int n_in,
                              void* d_out, int out_size) {
    const float* sem = (const float*)d_in[0];
    const float* emb = (const float*)d_in[1];
    const int*   cls = (const int*)d_in[2];
    const int*   lab = (const int*)d_in[3];
    float* out = (float*)d_out;

    prep_kernel<<<NTOT / 256, 256>>>(lab, cls);

    dim3 gf(SEG_X + CE_X, BATCH);
    fused_main<<<gf, 256>>>(emb, sem, cls);

    dim3 g3(296, BATCH);
    pull_kernel<<<g3, 256>>>(emb);

    final_kernel<<<1, 32>>>(out);
}

// round 10
// speedup vs baseline: 1.2975x; 1.0587x over previous
#include <cuda_runtime.h>
#include <math.h>

#define BATCH 2
#define NC 8
#define NE 16
#define NSEG 17
#define DD 64
#define HH 128
#define WW 128
#define NVOX (DD*HH*WW)      /* 1048576 per batch */
#define NTOT (BATCH*NVOX)

#define SEG_X 296            /* segstat blocks per batch in fused kernel */
#define CE_X  296            /* ce_dice blocks per batch in fused kernel */

// ---------------- scratch (device globals; zero-initialized at load) --------
__device__ int   g_packed[NTOT];       // label | (boundary ? sign bit : 0)
__device__ float g_nll;
__device__ float g_cardp[BATCH][NC];
__device__ float g_inter[BATCH][NC];
__device__ float g_hist[BATCH][NC];    // class counts (= cardg)
__device__ float g_cnt[BATCH][NSEG];
__device__ float g_bcnt[BATCH][NSEG];  // boundary counts per segment
__device__ float g_cnum[BATCH][NSEG][NE];
__device__ float g_pull[BATCH][NSEG];

// pack two f32 into bf16x2: low = x, high = y
__device__ __forceinline__ unsigned cvt_bf16x2(float x, float y) {
    unsigned d;
    asm("cvt.rn.bf16x2.f32 %0, %1, %2;" : "=r"(d) : "f"(y), "f"(x));
    return d;
}

// one-hot half: (label(p)==n) ? bf16(w(p)) : 0
__device__ __forceinline__ unsigned hb(int p, int n) {
    int l = p & 0x7fffffff;
    unsigned w = (p < 0) ? 0x4120u : 0x3F80u;   // bf16 10.0 : 1.0
    return (l == n) ? w : 0u;
}

// ------ prep: boundary + pack + segment/class histograms ------
__global__ void __launch_bounds__(256) prep_kernel(const int* __restrict__ lab,
                                                   const int* __restrict__ cls) {
    __shared__ float s_cnt[NSEG], s_bcnt[NSEG], s_hist[NC];
    if (threadIdx.x < NSEG) { s_cnt[threadIdx.x] = 0.f; s_bcnt[threadIdx.x] = 0.f; }
    if (threadIdx.x < NC) s_hist[threadIdx.x] = 0.f;
    __syncthreads();

    int idx = blockIdx.x * blockDim.x + threadIdx.x;
    int b = idx >> 20;
    int v = idx & (NVOX - 1);
    int d = v >> 14;
    int r = v & 16383;
    int h = r >> 7;
    int x = r & 127;
    const int* Lb = lab + (size_t)b * NVOX;
    int c0 = Lb[v];
    bool diff = false;
#pragma unroll
    for (int dd = -1; dd <= 1; dd++) {
        int zd = min(max(d + dd, 0), DD - 1);
#pragma unroll
        for (int dh = -1; dh <= 1; dh++) {
            int zh = min(max(h + dh, 0), HH - 1);
#pragma unroll
            for (int dx = -1; dx <= 1; dx++) {
                int zx = min(max(x + dx, 0), WW - 1);
                diff |= (Lb[(zd << 14) + (zh << 7) + zx] != c0);
            }
        }
    }
    g_packed[idx] = c0 | (diff ? 0x80000000 : 0);

    atomicAdd(&s_cnt[c0], 1.f);
    if (diff) atomicAdd(&s_bcnt[c0], 1.f);
    int cl = cls[idx];
    atomicAdd(&s_hist[cl], 1.f);

    __syncthreads();
    if (threadIdx.x < NSEG) {
        if (s_cnt[threadIdx.x]  != 0.f) atomicAdd(&g_cnt[b][threadIdx.x],  s_cnt[threadIdx.x]);
        if (s_bcnt[threadIdx.x] != 0.f) atomicAdd(&g_bcnt[b][threadIdx.x], s_bcnt[threadIdx.x]);
    }
    if (threadIdx.x < NC && s_hist[threadIdx.x] != 0.f)
        atomicAdd(&g_hist[b][threadIdx.x], s_hist[threadIdx.x]);
}

// ------- segstat body: one-hot GEMM via mma.m16n8k16.bf16 -------
__device__ __forceinline__ void segstat_body(const float* __restrict__ embed,
                                             int b, int bx) {
    const float* eb = embed + (size_t)b * NE * NVOX;
    const int*   pb = g_packed + (size_t)b * NVOX;

    int lane = threadIdx.x & 31;
    int warp = threadIdx.x >> 5;
    int gwarp = bx * 8 + warp;
    int nwarps = SEG_X * 8;

    int t  = lane & 3;       // k-group
    int gq = lane >> 2;      // channel/segment group 0..7

    float d[3][4];
#pragma unroll
    for (int f = 0; f < 3; f++)
#pragma unroll
        for (int r = 0; r < 4; r++) d[f][r] = 0.f;

    const float* r0base = eb + (size_t)gq * NVOX;
    const float* r1base = eb + (size_t)(gq + 8) * NVOX;

    for (int pp = gwarp; pp < NVOX/32; pp += nwarps) {
        int base0 = pp * 32 + 4 * t;
        int base1 = base0 + 16;
        int4   pA  = *(const int4*)(pb + base0);
        int4   pB  = *(const int4*)(pb + base1);
        float4 a0A = *(const float4*)(r0base + base0);
        float4 a1A = *(const float4*)(r1base + base0);
        float4 a0B = *(const float4*)(r0base + base1);
        float4 a1B = *(const float4*)(r1base + base1);

        unsigned A0 = cvt_bf16x2(a0A.x, a0A.y);
        unsigned A1 = cvt_bf16x2(a1A.x, a1A.y);
        unsigned A2 = cvt_bf16x2(a0A.z, a0A.w);
        unsigned A3 = cvt_bf16x2(a1A.z, a1A.w);
#pragma unroll
        for (int f = 0; f < 3; f++) {
            int n = gq + 8*f;
            unsigned B0 = hb(pA.x, n) | (hb(pA.y, n) << 16);
            unsigned B1 = hb(pA.z, n) | (hb(pA.w, n) << 16);
            asm volatile(
                "mma.sync.aligned.m16n8k16.row.col.f32.bf16.bf16.f32 "
                "{%0,%1,%2,%3}, {%4,%5,%6,%7}, {%8,%9}, {%0,%1,%2,%3};"
                : "+f"(d[f][0]), "+f"(d[f][1]), "+f"(d[f][2]), "+f"(d[f][3])
                : "r"(A0), "r"(A1), "r"(A2), "r"(A3), "r"(B0), "r"(B1));
        }
        unsigned C0 = cvt_bf16x2(a0B.x, a0B.y);
        unsigned C1 = cvt_bf16x2(a1B.x, a1B.y);
        unsigned C2 = cvt_bf16x2(a0B.z, a0B.w);
        unsigned C3 = cvt_bf16x2(a1B.z, a1B.w);
#pragma unroll
        for (int f = 0; f < 3; f++) {
            int n = gq + 8*f;
            unsigned B0 = hb(pB.x, n) | (hb(pB.y, n) << 16);
            unsigned B1 = hb(pB.z, n) | (hb(pB.w, n) << 16);
            asm volatile(
                "mma.sync.aligned.m16n8k16.row.col.f32.bf16.bf16.f32 "
                "{%0,%1,%2,%3}, {%4,%5,%6,%7}, {%8,%9}, {%0,%1,%2,%3};"
                : "+f"(d[f][0]), "+f"(d[f][1]), "+f"(d[f][2]), "+f"(d[f][3])
                : "r"(C0), "r"(C1), "r"(C2), "r"(C3), "r"(B0), "r"(B1));
        }
    }

    __shared__ float s_cnum[NSEG][NE];
    for (int j = threadIdx.x; j < NSEG*NE; j += blockDim.x) (&s_cnum[0][0])[j] = 0.f;
    __syncthreads();
#pragma unroll
    for (int f = 0; f < 3; f++) {
        int n0 = 8*f + 2*t;
        if (n0 < NSEG) {
            atomicAdd(&s_cnum[n0][gq],     d[f][0]);
            atomicAdd(&s_cnum[n0][gq + 8], d[f][2]);
        }
        if (n0 + 1 < NSEG) {
            atomicAdd(&s_cnum[n0+1][gq],     d[f][1]);
            atomicAdd(&s_cnum[n0+1][gq + 8], d[f][3]);
        }
    }
    __syncthreads();
    for (int j = threadIdx.x; j < NSEG*NE; j += blockDim.x) {
        float v = (&s_cnum[0][0])[j];
        if (v != 0.f) atomicAdd(&g_cnum[b][0][0] + j, v);
    }
}

// ------- ce_dice body: float2 (2 voxels/thread/iter) to fit registers -------
__device__ __forceinline__ void ce_body(const float* __restrict__ logits,
                                        const int* __restrict__ cls,
                                        int b, int bx) {
    const float2* lb = (const float2*)(logits + (size_t)b * NC * NVOX);
    const int2*   cb = (const int2*)(cls + (size_t)b * NVOX);

    float r_nll = 0.f;
    float r_cardp[NC], r_inter[NC];
#pragma unroll
    for (int c = 0; c < NC; c++) { r_cardp[c]=0.f; r_inter[c]=0.f; }

    int stride = CE_X * 256;
    for (int i = bx * 256 + threadIdx.x; i < NVOX/2; i += stride) {
        int2 t2 = cb[i];
        float2 x2[NC];
#pragma unroll
        for (int c = 0; c < NC; c++) x2[c] = lb[(size_t)c * (NVOX/2) + i];
#pragma unroll
        for (int j = 0; j < 2; j++) {
            float xv[NC];
#pragma unroll
            for (int c = 0; c < NC; c++)
                xv[c] = j ? x2[c].y : x2[c].x;
            int t = j ? t2.y : t2.x;

            float m = xv[0];
#pragma unroll
            for (int c = 1; c < NC; c++) m = fmaxf(m, xv[c]);
            float ex[NC]; float s = 0.f;
#pragma unroll
            for (int c = 0; c < NC; c++) { ex[c] = __expf(xv[c] - m); s += ex[c]; }
            float inv = 1.0f / s;
            float lse = m + __logf(s);
#pragma unroll
            for (int c = 0; c < NC; c++) {
                float p = ex[c] * inv;
                r_cardp[c] += p;
                if (t == c) {
                    r_inter[c] += p;
                    r_nll += lse - xv[c];
                }
            }
        }
    }

    __shared__ float s_acc[17];
    if (threadIdx.x < 17) s_acc[threadIdx.x] = 0.f;
    __syncthreads();
    float vals[17];
    vals[0] = r_nll;
#pragma unroll
    for (int c = 0; c < NC; c++) { vals[1+c]=r_cardp[c]; vals[9+c]=r_inter[c]; }
#pragma unroll
    for (int k = 0; k < 17; k++) {
        float v = vals[k];
#pragma unroll
        for (int o = 16; o; o >>= 1) v += __shfl_xor_sync(0xffffffffu, v, o);
        if ((threadIdx.x & 31) == 0) atomicAdd(&s_acc[k], v);
    }
    __syncthreads();
    int t = threadIdx.x;
    if (t == 0)       atomicAdd(&g_nll, s_acc[0]);
    else if (t < 9)   atomicAdd(&g_cardp[b][t-1], s_acc[t]);
    else if (t < 17)  atomicAdd(&g_inter[b][t-9], s_acc[t]);
}

// ------- fused main pass: segstat blocks + ce_dice blocks in one launch -----
__global__ void __launch_bounds__(256, 4) fused_main(const float* __restrict__ embed,
                                                     const float* __restrict__ logits,
                                                     const int* __restrict__ cls) {
    int b = blockIdx.y;
    if (blockIdx.x < SEG_X) segstat_body(embed, b, blockIdx.x);
    else                    ce_body(logits, cls, b, blockIdx.x - SEG_X);
}

// ---------------- pass B: pull (centers computed per block) ----------------
__global__ void __launch_bounds__(256, 2) pull_kernel(const float* __restrict__ embed) {
    int b = blockIdx.y;
    __shared__ float sc[NSEG][NE + 1];
    __shared__ float s_pull[NSEG];
    for (int j = threadIdx.x; j < NSEG*NE; j += blockDim.x) {
        int k = j / NE, c = j % NE;
        float wsum = g_cnt[b][k] + 9.0f * g_bcnt[b][k];
        sc[k][c] = g_cnum[b][k][c] / (wsum + 1e-8f);
    }
    for (int j = threadIdx.x; j < NSEG; j += blockDim.x) s_pull[j] = 0.f;
    __syncthreads();

    const float4* eb = (const float4*)(embed + (size_t)b * NE * NVOX);
    const int4*   pb = (const int4*)(g_packed + (size_t)b * NVOX);

    int stride = gridDim.x * blockDim.x;
    for (int i = blockIdx.x * blockDim.x + threadIdx.x; i < NVOX/4; i += stride) {
        int4 p4 = pb[i];
        float4 e4[NE];
#pragma unroll
        for (int c = 0; c < NE; c++)
            e4[c] = eb[(size_t)c * (NVOX/4) + i];

        int   lv[4]; float wv[4]; float ds[4];
#pragma unroll
        for (int j = 0; j < 4; j++) {
            int p = (j==0) ? p4.x : (j==1) ? p4.y : (j==2) ? p4.z : p4.w;
            lv[j] = p & 0x7fffffff;
            wv[j] = (p < 0) ? 10.f : 1.f;
            ds[j] = 0.f;
        }
#pragma unroll
        for (int c = 0; c < NE; c++) {
#pragma unroll
            for (int j = 0; j < 4; j++) {
                float ev = (j==0) ? e4[c].x : (j==1) ? e4[c].y : (j==2) ? e4[c].z : e4[c].w;
                float dv = ev - sc[lv[j]][c];
                ds[j] += dv * dv;
            }
        }
#pragma unroll
        for (int j = 0; j < 4; j++) {
            float dist = sqrtf(ds[j]);
            float tt = fmaxf(dist - 0.5f, 0.f);
            atomicAdd(&s_pull[lv[j]], tt * tt * wv[j]);
        }
    }
    __syncthreads();
    for (int j = threadIdx.x; j < NSEG; j += blockDim.x)
        atomicAdd(&g_pull[b][j], s_pull[j]);
}

// -------- final: centers/push/norm + combine + self-clean (512 threads) -----
__global__ void __launch_bounds__(512) final_kernel(float* __restrict__ out) {
    int tid = threadIdx.x;
    int lane = tid & 31;
    int warp = tid >> 5;
    __shared__ float sc[BATCH][NSEG][NE];
    __shared__ float s_lp[BATCH], s_push[BATCH], s_norm[BATCH], s_val[BATCH];

    // centers for both batches, block-wide (2*272 loads over 512 threads)
    for (int j = tid; j < BATCH*NSEG*NE; j += 512) {
        int b = j / (NSEG*NE);
        int k = (j / NE) % NSEG;
        int c = j % NE;
        float wsum = g_cnt[b][k] + 9.0f * g_bcnt[b][k];
        sc[b][k][c] = g_cnum[b][k][c] / (wsum + 1e-8f);
    }
    __syncthreads();

    // warp b (b < BATCH) does per-batch reductions concurrently
    if (warp < BATCH) {
        int b = warp;
        int pres_lane = (lane >= 1 && lane < NSEG) ? (g_cnt[b][lane] > 0.f ? 1 : 0) : 0;
        unsigned mask = __ballot_sync(0xffffffffu, pres_lane);
        float np = (float)__popc(mask);

        float lp = pres_lane ? g_pull[b][lane] / fmaxf(g_cnt[b][lane], 1.f) : 0.f;
#pragma unroll
        for (int o = 16; o; o >>= 1) lp += __shfl_xor_sync(0xffffffffu, lp, o);

        float pacc = 0.f;
        for (int pp = lane; pp < 120; pp += 32) {
            int i = 1, rem = pp;
            while (rem >= (NSEG - 1) - i) { rem -= (NSEG - 1) - i; i++; }
            int jj = i + 1 + rem;
            float ds = 0.f;
#pragma unroll
            for (int c = 0; c < NE; c++) { float dv = sc[b][i][c] - sc[b][jj][c]; ds += dv * dv; }
            float pw = sqrtf(ds);
            float tt = fmaxf(3.0f - pw, 0.f);
            if (((mask >> i) & 1) && ((mask >> jj) & 1)) pacc += tt * tt;
        }
#pragma unroll
        for (int o = 16; o; o >>= 1) pacc += __shfl_xor_sync(0xffffffffu, pacc, o);

        float nacc = 0.f;
        if (pres_lane) {
            float ds = 0.f;
#pragma unroll
            for (int c = 0; c < NE; c++) ds += sc[b][lane][c] * sc[b][lane][c];
            nacc = sqrtf(ds);
        }
#pragma unroll
        for (int o = 16; o; o >>= 1) nacc += __shfl_xor_sync(0xffffffffu, nacc, o);

        if (lane == 0) {
            float npairs = np * (np - 1.f) * 0.5f;
            s_lp[b]   = lp;
            s_push[b] = (npairs > 0.f) ? pacc / fmaxf(npairs, 1.f) : 0.f;
            s_norm[b] = (np > 0.f)     ? nacc / fmaxf(np, 1.f)     : 0.f;
            s_val[b]  = (np > 0.f) ? 1.f : 0.f;
        }
    }
    __syncthreads();

    if (tid == 0) {
        float lp_sum = 0.f, push_sum = 0.f, norm_sum = 0.f, val_sum = 0.f;
        for (int b = 0; b < BATCH; b++) {
            lp_sum += s_lp[b]; push_sum += s_push[b];
            norm_sum += s_norm[b]; val_sum += s_val[b];
        }
        float Nf = (float)NTOT;
        float ce = g_nll / Nf;
        float dsum = 0.f;
        for (int b = 0; b < BATCH; b++)
            for (int c = 0; c < NC; c++)
                dsum += (2.0f * g_inter[b][c] + 1e-5f) /
                        (g_cardp[b][c] + g_hist[b][c] + 1e-5f);
        float dice = 1.0f - dsum / (float)(BATCH * NC);

        float ins = (lp_sum + push_sum + 0.001f * norm_sum) / fmaxf(val_sum, 1.f);
        float sem = ce + dice;
        out[0] = sem + ins;
        out[1] = sem;
        out[2] = ce;
        out[3] = dice;
        out[4] = ins;
    }
    __syncthreads();

    // self-clean accumulators so the next graph replay starts from zero
    for (int j = tid; j < BATCH*NC; j += 512) {
        (&g_cardp[0][0])[j] = 0.f;
        (&g_inter[0][0])[j] = 0.f;
        (&g_hist[0][0])[j]  = 0.f;
    }
    for (int j = tid; j < BATCH*NSEG; j += 512) {
        (&g_cnt[0][0])[j]  = 0.f;
        (&g_bcnt[0][0])[j] = 0.f;
        (&g_pull[0][0])[j] = 0.f;
    }
    for (int j = tid; j < BATCH*NSEG*NE; j += 512)
        (&g_cnum[0][0][0])[j] = 0.f;
    if (tid == 0) g_nll = 0.f;
}

// ---------------- launch ----------------
extern "C" void kernel_launch(void* const* d_in, const int* in_sizes, int n_in,
                              void* d_out, int out_size) {
    const float* sem = (const float*)d_in[0];
    const float* emb = (const float*)d_in[1];
    const int*   cls = (const int*)d_in[2];
    const int*   lab = (const int*)d_in[3];
    float* out = (float*)d_out;

    prep_kernel<<<NTOT / 256, 256>>>(lab, cls);

    dim3 gf(SEG_X + CE_X, BATCH);
    fused_main<<<gf, 256>>>(emb, sem, cls);

    dim3 g3(592, BATCH);
    pull_kernel<<<g3, 256>>>(emb);

    final_kernel<<<1, 512>>>(out);
}